// round 16
// baseline (speedup 1.0000x reference)
#include <cuda_runtime.h>
#include <cuda_bf16.h>
#include <cstdint>

#define NBLK 296
#define NTILE 1024

// smem strides (bf16 elems)
#define LDA1 136   // P1 F_mod: [c][w]
#define LDB1 72    // P1 Win:   [o][c]
#define LDS1 136   // P1 staging [o][w]
#define LDA3 136   // P3 h_sum: [o][w]
#define LDB3 136   // P3 Wout:  [c][o]
#define LDP  132   // P3 fp32 staging [c][w]
#define LDK2 136   // P2 planes [h][w]

// phase smem offsets (bytes); dyn smem = 104448
#define P1_SW 0
#define P1_XF 18432
#define P1_F  51200
#define P1_PB 68608
#define P2_X  0
#define P2_H  34816
#define P2_V  69632
#define P3_WO 0
#define P3_HS 17408
#define P3_R  17408

// ---- scratch (device globals; allocation-free) ----
__device__ __nv_bfloat16 g_xp[8*128*128*128];  // x_proj [b][h][o][w]
__device__ __nv_bfloat16 g_hs[8*128*128*128];  // h_sum  [b][h][o][w]
__device__ int g_bar[2];

__device__ __forceinline__ uint32_t smem_u32(const void* p) {
    return (uint32_t)__cvta_generic_to_shared(p);
}

#define CP_ASYNC16(dst, src) \
    asm volatile("cp.async.cg.shared.global [%0], [%1], 16;" \
                 :: "r"(dst), "l"(src) : "memory")
#define CP_COMMIT() asm volatile("cp.async.commit_group;" ::: "memory")
#define CP_WAIT0()  asm volatile("cp.async.wait_group 0;" ::: "memory")

__device__ __forceinline__ void ldsm_x4_trans(uint32_t* r, uint32_t a) {
    asm volatile("ldmatrix.sync.aligned.m8n8.x4.trans.shared.b16 {%0,%1,%2,%3}, [%4];"
        : "=r"(r[0]), "=r"(r[1]), "=r"(r[2]), "=r"(r[3]) : "r"(a));
}
__device__ __forceinline__ void ldsm_x4(uint32_t* r, uint32_t a) {
    asm volatile("ldmatrix.sync.aligned.m8n8.x4.shared.b16 {%0,%1,%2,%3}, [%4];"
        : "=r"(r[0]), "=r"(r[1]), "=r"(r[2]), "=r"(r[3]) : "r"(a));
}
__device__ __forceinline__ void mma_bf16(float* d, const uint32_t* a, const uint32_t* b) {
    asm volatile("mma.sync.aligned.m16n8k16.row.col.f32.bf16.bf16.f32 "
        "{%0,%1,%2,%3}, {%4,%5,%6,%7}, {%8,%9}, {%0,%1,%2,%3};"
        : "+f"(d[0]), "+f"(d[1]), "+f"(d[2]), "+f"(d[3])
        : "r"(a[0]), "r"(a[1]), "r"(a[2]), "r"(a[3]), "r"(b[0]), "r"(b[1]));
}

__device__ __forceinline__ float prior_at(const float* __restrict__ prior,
                                          int b, int h, int w) {
    const float s = 31.0f / 127.0f;
    float ys = h * s, xs = w * s;
    int y0 = (int)ys, x0 = (int)xs;
    int y1 = min(y0 + 1, 31), x1 = min(x0 + 1, 31);
    float wy = ys - (float)y0, wx = xs - (float)x0;
    const float* p = prior + b * 1024;
    float p00 = p[y0*32+x0], p01 = p[y0*32+x1];
    float p10 = p[y1*32+x0], p11 = p[y1*32+x1];
    float top = p00 + (p01 - p00) * wx;
    float bot = p10 + (p11 - p10) * wx;
    float v = top + (bot - top) * wy;
    return fminf(1.0f, fmaxf(-1.0f, v));
}

// global barrier: all NBLK blocks resident by construction (launch_bounds(512,2))
__device__ __forceinline__ void gbarrier(int idx) {
    __syncthreads();
    if (threadIdx.x == 0) {
        __threadfence();
        atomicAdd(&g_bar[idx], 1);
        volatile int* vc = &g_bar[idx];
        while (*vc < NBLK) { }
    }
    __syncthreads();
}

__global__ __launch_bounds__(512, 2) void kfused(
    const float* __restrict__ x, const float* __restrict__ prior,
    const float* __restrict__ Win, const float* __restrict__ b_in,
    const float* __restrict__ A, const float* __restrict__ Bvec,
    const float* __restrict__ alpha_p, const float* __restrict__ gamma_p,
    const float* __restrict__ Wout, const float* __restrict__ b_out,
    float* __restrict__ out)
{
    extern __shared__ __align__(16) char smch[];
    __shared__ float s_pr[128], s_bin[128], s_bo[64];
    __shared__ float s_pow[64], s_cH[128], s_cV[128];

    const int t = threadIdx.x;
    const int wid = t >> 5, lid = t & 31;
    const int bid = blockIdx.x;
    const float alpha = __ldg(alpha_p), gamma = __ldg(gamma_p);

    // ================= PHASE 1: x_proj = F_mod @ Win^T + b_in =================
    {
        __nv_bfloat16* sW  = (__nv_bfloat16*)(smch + P1_SW);
        float*         sXf = (float*)(smch + P1_XF);
        __nv_bfloat16* sF  = (__nv_bfloat16*)(smch + P1_F);
        __nv_bfloat16* sPb = (__nv_bfloat16*)(smch + P1_PB);

#pragma unroll
        for (int i = 0; i < 4; i++) {
            int idx = t + i * 512;           // 2048 = 128o x 16 c4
            int o = idx >> 4, c4 = (idx & 15) * 4;
            float4 wv = *(const float4*)&Win[o * 64 + c4];
            __nv_bfloat162 p0 = __float22bfloat162_rn(make_float2(wv.x, wv.y));
            __nv_bfloat162 p1 = __float22bfloat162_rn(make_float2(wv.z, wv.w));
            *(uint2*)&sW[o * LDB1 + c4] = make_uint2(*(uint32_t*)&p0, *(uint32_t*)&p1);
        }
        if (t < 128) s_bin[t] = b_in[t];
        __syncthreads();

        for (int tile = bid; tile < NTILE; tile += NBLK) {
            const int b = tile >> 7, h = tile & 127;

            {   // cp.async x row (32KB)
                const float* xrow = x + b * 1048576 + h * 128;
                const uint32_t sXf_u = smem_u32(sXf);
#pragma unroll
                for (int i = 0; i < 4; i++) {
                    int idx = t + i * 512;
                    int c = idx >> 5, ch = (idx & 31) * 4;
                    CP_ASYNC16(sXf_u + (uint32_t)(idx * 16), &xrow[c * 16384 + ch]);
                }
                CP_COMMIT();
            }
            if (t < 128) s_pr[t] = prior_at(prior, b, h, t);
            CP_WAIT0();
            __syncthreads();

#pragma unroll
            for (int i = 0; i < 4; i++) {    // sF <- F_mod bf16 [c][w]
                int idx = t + i * 512;
                int c = idx >> 5, w4 = (idx & 31) * 4;
                float4 f = *(const float4*)&sXf[c * 128 + w4];
                float4 pv = *(const float4*)&s_pr[w4];
                f.x += alpha * pv.x; f.y += alpha * pv.y;
                f.z += alpha * pv.z; f.w += alpha * pv.w;
                __nv_bfloat162 p0 = __float22bfloat162_rn(make_float2(f.x, f.y));
                __nv_bfloat162 p1 = __float22bfloat162_rn(make_float2(f.z, f.w));
                *(uint2*)&sF[c * LDA1 + w4] = make_uint2(*(uint32_t*)&p0, *(uint32_t*)&p1);
            }
            __syncthreads();

            // MMA: m=o (8 m-tiles x 2 w-halves), n=w, K=64
            const int o0 = (wid & 7) * 16;
            const int nh = wid >> 3;
            float acc[8][4];
#pragma unroll
            for (int nt = 0; nt < 8; nt++)
#pragma unroll
                for (int j = 0; j < 4; j++) acc[nt][j] = 0.f;

            const uint32_t sF_u = smem_u32(sF), sW_u = smem_u32(sW);
            const uint32_t a_base = sW_u +
                (uint32_t)(((o0 + (lid & 15)) * LDB1 + ((lid >> 4) << 3)) * 2);
            const int b_row = (lid & 7) + (((lid >> 3) & 1) << 3);
            const int b_col = nh * 64 + ((lid >> 4) << 3);
            const uint32_t b_base = sF_u + (uint32_t)((b_row * LDA1 + b_col) * 2);

#pragma unroll
            for (int ks = 0; ks < 4; ks++) {
                uint32_t afr[4];
                ldsm_x4(afr, a_base + (uint32_t)(ks * 16 * 2));
#pragma unroll
                for (int nt16 = 0; nt16 < 4; nt16++) {
                    uint32_t bfr[4];
                    ldsm_x4_trans(bfr, b_base + (uint32_t)((ks * 16 * LDA1 + nt16 * 16) * 2));
                    mma_bf16(acc[2 * nt16],     afr, bfr);
                    mma_bf16(acc[2 * nt16 + 1], afr, bfr + 2);
                }
            }
            __syncthreads();

            {   // acc (+bias) -> sPb[o][w]
                const int g = lid >> 2, q2 = (lid & 3) * 2;
                const int oA = o0 + g, oB = o0 + g + 8;
                const float bA = s_bin[oA], bB = s_bin[oB];
#pragma unroll
                for (int nt = 0; nt < 8; nt++) {
                    int w = nh * 64 + nt * 8 + q2;
                    __nv_bfloat162 pA = __float22bfloat162_rn(
                        make_float2(acc[nt][0] + bA, acc[nt][1] + bA));
                    __nv_bfloat162 pB = __float22bfloat162_rn(
                        make_float2(acc[nt][2] + bB, acc[nt][3] + bB));
                    *(__nv_bfloat162*)&sPb[oA * LDS1 + w] = pA;
                    *(__nv_bfloat162*)&sPb[oB * LDS1 + w] = pB;
                }
            }
            __syncthreads();

            {   // x_proj write-out
                __nv_bfloat16* xp = g_xp + (b * 128 + h) * 16384;
#pragma unroll
                for (int i = 0; i < 4; i++) {
                    int idx = t + i * 512;
                    int o = idx >> 4, c8 = (idx & 15) * 8;
                    *(uint4*)&xp[o * 128 + c8] = *(const uint4*)&sPb[o * LDS1 + c8];
                }
            }
            __syncthreads();
        }
    }

    gbarrier(0);

    // ===== PHASE 2: dual scan per (b,o) plane — split scans + pow correction =====
    {
        __nv_bfloat16* sX = (__nv_bfloat16*)(smch + P2_X);
        __nv_bfloat16* sH = (__nv_bfloat16*)(smch + P2_H);
        __nv_bfloat16* sV = (__nv_bfloat16*)(smch + P2_V);

        for (int pl = bid; pl < NTILE; pl += NBLK) {
            const int b = pl >> 7, o = pl & 127;
            const float a = tanhf(__ldg(&A[o]));
            const float bv = __ldg(&Bvec[o]);
            const int gbase = b * 2097152 + o * 128;

            {   // async load plane
                const __nv_bfloat16* src = g_xp + gbase;
                const uint32_t sX_u = smem_u32(sX);
#pragma unroll
                for (int i = 0; i < 4; i++) {
                    int idx = t + i * 512;
                    int h = idx >> 4, c8 = (idx & 15) * 8;
                    CP_ASYNC16(sX_u + (uint32_t)((h * LDK2 + c8) * 2),
                               &src[h * 16384 + c8]);
                }
                CP_COMMIT();
            }
            if (t < 64) {   // s_pow[k] = a^(k+1), binary exponentiation
                float p = 1.f, base = a;
                int e = t + 1;
                while (e) { if (e & 1) p *= base; base *= base; e >>= 1; }
                s_pow[t] = p;
            }
            CP_WAIT0();
            __syncthreads();

            if (t < 256) {
                // warps 0-7: h-scan. row = t&127, half = t>>7, 64 steps.
                const int row = t & 127, half = t >> 7;
                const __nv_bfloat16* xr = &sX[row * LDK2 + half * 64];
                __nv_bfloat16* hr = &sH[row * LDK2 + half * 64];
                float st = 0.0f;
#pragma unroll 4
                for (int wb = 0; wb < 16; wb++) {
                    uint2 u = *(const uint2*)&xr[wb * 4];
                    float2 f0 = __bfloat1622float2(*(__nv_bfloat162*)&u.x);
                    float2 f1 = __bfloat1622float2(*(__nv_bfloat162*)&u.y);
                    st = fmaf(a, st, bv * f0.x); f0.x = st;
                    st = fmaf(a, st, bv * f0.y); f0.y = st;
                    st = fmaf(a, st, bv * f1.x); f1.x = st;
                    st = fmaf(a, st, bv * f1.y); f1.y = st;
                    __nv_bfloat162 p0 = __float22bfloat162_rn(f0);
                    __nv_bfloat162 p1 = __float22bfloat162_rn(f1);
                    *(uint2*)&hr[wb * 4] = make_uint2(*(uint32_t*)&p0, *(uint32_t*)&p1);
                }
                if (half == 0) s_cH[row] = st;
            } else {
                // warps 8-15: v-scan. col = idx&127, half = idx>>7, 64 steps.
                const int idx = t - 256;
                const int col = idx & 127, half = idx >> 7;
                const int h0 = half * 64;
                float st = 0.0f;
#pragma unroll 4
                for (int j = 0; j < 64; j++) {
                    int h = h0 + j;
                    float xvv = __bfloat162float(sX[h * LDK2 + col]);
                    st = fmaf(a, st, bv * xvv);
                    sV[h * LDK2 + col] = __float2bfloat16(st);
                }
                if (half == 0) s_cV[col] = st;
            }
            __syncthreads();

            {   // merge + corrections + store
                __nv_bfloat16* dst = g_hs + gbase;
#pragma unroll
                for (int i = 0; i < 4; i++) {
                    int idx = t + i * 512;
                    int h = idx >> 4, c8 = (idx & 15) * 8;
                    uint4 uh = *(const uint4*)&sH[h * LDK2 + c8];
                    uint4 uv = *(const uint4*)&sV[h * LDK2 + c8];
                    float2 h0 = __bfloat1622float2(*(__nv_bfloat162*)&uh.x);
                    float2 h1 = __bfloat1622float2(*(__nv_bfloat162*)&uh.y);
                    float2 h2 = __bfloat1622float2(*(__nv_bfloat162*)&uh.z);
                    float2 h3 = __bfloat1622float2(*(__nv_bfloat162*)&uh.w);
                    float2 v0 = __bfloat1622float2(*(__nv_bfloat162*)&uv.x);
                    float2 v1 = __bfloat1622float2(*(__nv_bfloat162*)&uv.y);
                    float2 v2 = __bfloat1622float2(*(__nv_bfloat162*)&uv.z);
                    float2 v3 = __bfloat1622float2(*(__nv_bfloat162*)&uv.w);
                    float fv[8] = { h0.x+v0.x, h0.y+v0.y, h1.x+v1.x, h1.y+v1.y,
                                    h2.x+v2.x, h2.y+v2.y, h3.x+v3.x, h3.y+v3.y };
                    if (c8 >= 64) {          // h-scan upper-half correction
                        float ch = s_cH[h];
                        float4 pw0 = *(const float4*)&s_pow[c8 - 64];
                        float4 pw1 = *(const float4*)&s_pow[c8 - 60];
                        fv[0] = fmaf(pw0.x, ch, fv[0]);
                        fv[1] = fmaf(pw0.y, ch, fv[1]);
                        fv[2] = fmaf(pw0.z, ch, fv[2]);
                        fv[3] = fmaf(pw0.w, ch, fv[3]);
                        fv[4] = fmaf(pw1.x, ch, fv[4]);
                        fv[5] = fmaf(pw1.y, ch, fv[5]);
                        fv[6] = fmaf(pw1.z, ch, fv[6]);
                        fv[7] = fmaf(pw1.w, ch, fv[7]);
                    }
                    if (h >= 64) {           // v-scan upper-half correction
                        float ph = s_pow[h - 64];
                        float4 cv0 = *(const float4*)&s_cV[c8];
                        float4 cv1 = *(const float4*)&s_cV[c8 + 4];
                        fv[0] = fmaf(ph, cv0.x, fv[0]);
                        fv[1] = fmaf(ph, cv0.y, fv[1]);
                        fv[2] = fmaf(ph, cv0.z, fv[2]);
                        fv[3] = fmaf(ph, cv0.w, fv[3]);
                        fv[4] = fmaf(ph, cv1.x, fv[4]);
                        fv[5] = fmaf(ph, cv1.y, fv[5]);
                        fv[6] = fmaf(ph, cv1.z, fv[6]);
                        fv[7] = fmaf(ph, cv1.w, fv[7]);
                    }
                    uint4 r;
                    __nv_bfloat162 q0 = __float22bfloat162_rn(make_float2(fv[0], fv[1]));
                    __nv_bfloat162 q1 = __float22bfloat162_rn(make_float2(fv[2], fv[3]));
                    __nv_bfloat162 q2 = __float22bfloat162_rn(make_float2(fv[4], fv[5]));
                    __nv_bfloat162 q3 = __float22bfloat162_rn(make_float2(fv[6], fv[7]));
                    r.x = *(uint32_t*)&q0; r.y = *(uint32_t*)&q1;
                    r.z = *(uint32_t*)&q2; r.w = *(uint32_t*)&q3;
                    *(uint4*)&dst[h * 16384 + c8] = r;
                }
            }
            __syncthreads();
        }
    }

    gbarrier(1);

    // ================= PHASE 3: out = x + a*pr + g*(h_sum @ Wout^T + b) ======
    {
        __nv_bfloat16* sWo = (__nv_bfloat16*)(smch + P3_WO);
        __nv_bfloat16* sHs = (__nv_bfloat16*)(smch + P3_HS);
        float* sR = (float*)(smch + P3_R);

#pragma unroll
        for (int i = 0; i < 4; i++) {
            int idx = t + i * 512;           // 2048 = 64c x 32 o4
            int c = idx >> 5, o4 = (idx & 31) * 4;
            float4 wv = *(const float4*)&Wout[c * 128 + o4];
            __nv_bfloat162 p0 = __float22bfloat162_rn(make_float2(wv.x, wv.y));
            __nv_bfloat162 p1 = __float22bfloat162_rn(make_float2(wv.z, wv.w));
            *(uint2*)&sWo[c * LDB3 + o4] = make_uint2(*(uint32_t*)&p0, *(uint32_t*)&p1);
        }
        if (t < 64) s_bo[t] = b_out[t];
        __syncthreads();

        for (int tile = bid; tile < NTILE; tile += NBLK) {
            const int b = tile >> 7, h = tile & 127;
            const int base_bh = b * 1048576 + h * 128;

            {   // cp.async sHs <- h_sum [o][w]
                const __nv_bfloat16* hs = g_hs + (b * 128 + h) * 16384;
                const uint32_t sHs_u = smem_u32(sHs);
#pragma unroll
                for (int i = 0; i < 4; i++) {
                    int idx = t + i * 512;
                    int o = idx >> 4, w8 = (idx & 15) * 8;
                    CP_ASYNC16(sHs_u + (uint32_t)((o * LDA3 + w8) * 2),
                               &hs[o * 128 + w8]);
                }
                CP_COMMIT();
            }
            if (t < 128) s_pr[t] = prior_at(prior, b, h, t);

            float4 xv[4];
#pragma unroll
            for (int i = 0; i < 4; i++) {
                int idx = t + i * 512;
                int c = idx >> 5, w4 = (idx & 31) * 4;
                xv[i] = *(const float4*)&x[base_bh + c * 16384 + w4];
            }
            CP_WAIT0();
            __syncthreads();

            // MMA: m=c (4 m-tiles x 4 w-quarters), n=w, K=128
            const int c0 = (wid & 3) * 16;
            const int q = wid >> 2;
            float acc[4][4];
#pragma unroll
            for (int nt = 0; nt < 4; nt++)
#pragma unroll
                for (int j = 0; j < 4; j++) acc[nt][j] = 0.f;

            const uint32_t sHs_u = smem_u32(sHs), sWo_u = smem_u32(sWo);
            const uint32_t a_base = sWo_u +
                (uint32_t)(((c0 + (lid & 15)) * LDB3 + ((lid >> 4) << 3)) * 2);
            const int b_row = (lid & 7) + (((lid >> 3) & 1) << 3);
            const int b_col = q * 32 + ((lid >> 4) << 3);
            const uint32_t b_base = sHs_u + (uint32_t)((b_row * LDA3 + b_col) * 2);

#pragma unroll
            for (int ks = 0; ks < 8; ks++) {
                uint32_t afr[4];
                ldsm_x4(afr, a_base + (uint32_t)(ks * 16 * 2));
#pragma unroll
                for (int nt16 = 0; nt16 < 2; nt16++) {
                    uint32_t bfr[4];
                    ldsm_x4_trans(bfr, b_base + (uint32_t)((ks * 16 * LDA3 + nt16 * 16) * 2));
                    mma_bf16(acc[2 * nt16],     afr, bfr);
                    mma_bf16(acc[2 * nt16 + 1], afr, bfr + 2);
                }
            }
            __syncthreads();

            {   // acc -> sR[c][w]
                const int g = lid >> 2, q2 = (lid & 3) * 2;
                const int cA = c0 + g, cB = c0 + g + 8;
#pragma unroll
                for (int nt = 0; nt < 4; nt++) {
                    int w = q * 32 + nt * 8 + q2;
                    *(float2*)&sR[cA * LDP + w] = make_float2(acc[nt][0], acc[nt][1]);
                    *(float2*)&sR[cB * LDP + w] = make_float2(acc[nt][2], acc[nt][3]);
                }
            }
            __syncthreads();

            {   // fused epilogue
#pragma unroll
                for (int i = 0; i < 4; i++) {
                    int idx = t + i * 512;
                    int c = idx >> 5, w4 = (idx & 31) * 4;
                    int gb = base_bh + c * 16384 + w4;
                    float4 rv = *(const float4*)&sR[c * LDP + w4];
                    float4 pv = *(const float4*)&s_pr[w4];
                    float bo = s_bo[c];
                    float4 r;
                    r.x = fmaf(alpha, pv.x, xv[i].x) + gamma * (rv.x + bo);
                    r.y = fmaf(alpha, pv.y, xv[i].y) + gamma * (rv.y + bo);
                    r.z = fmaf(alpha, pv.z, xv[i].z) + gamma * (rv.z + bo);
                    r.w = fmaf(alpha, pv.w, xv[i].w) + gamma * (rv.w + bo);
                    *(float4*)&out[gb] = r;
                }
            }
            __syncthreads();
        }
    }
}

extern "C" void kernel_launch(void* const* d_in, const int* in_sizes, int n_in,
                              void* d_out, int out_size) {
    const float* x      = (const float*)d_in[0];
    const float* prior  = (const float*)d_in[1];
    const float* W_in   = (const float*)d_in[2];
    const float* b_in   = (const float*)d_in[3];
    const float* A      = (const float*)d_in[4];
    const float* B      = (const float*)d_in[5];
    const float* alpha  = (const float*)d_in[6];
    const float* gamma  = (const float*)d_in[7];
    const float* W_out  = (const float*)d_in[8];
    const float* b_out  = (const float*)d_in[9];
    float* out = (float*)d_out;

    void* bar_addr = nullptr;
    cudaGetSymbolAddress(&bar_addr, g_bar);
    cudaMemsetAsync(bar_addr, 0, 2 * sizeof(int));

    const int smem = 104448;
    cudaFuncSetAttribute(kfused, cudaFuncAttributeMaxDynamicSharedMemorySize, smem);
    kfused<<<NBLK, 512, smem>>>(x, prior, W_in, b_in, A, B,
                                alpha, gamma, W_out, b_out, out);
}

// round 17
// speedup vs baseline: 1.0158x; 1.0158x over previous
#include <cuda_runtime.h>
#include <cuda_bf16.h>
#include <cstdint>

#define NBLK 296
#define NTILE 1024

// smem strides (bf16 elems)
#define LDA1 136   // P1 F_mod: [c][w]
#define LDB1 72    // P1 Win:   [o][c]
#define LDS1 136   // P1 staging [o][w]
#define LDA3 136   // P3 h_sum: [o][w]
#define LDB3 136   // P3 Wout:  [c][o]
#define LDP  132   // P3 fp32 staging [c][w]
#define LDK2 136   // P2 planes [h][w]

// phase smem offsets (bytes); dyn smem = 104448
#define P1_SW 0
#define P1_XF 18432
#define P1_F  51200
#define P1_PB 68608
#define P2_X  0
#define P2_H  34816
#define P2_V  69632
#define P3_WO 0
#define P3_HS 17408
#define P3_R  52224   // separate region -> sHs free during epilogue (prefetch target)

// ---- scratch (device globals; allocation-free) ----
__device__ __nv_bfloat16 g_xp[8*128*128*128];  // x_proj [b][h][o][w]
__device__ __nv_bfloat16 g_hs[8*128*128*128];  // h_sum  [b][h][o][w]
__device__ int g_bar[2];

__device__ __forceinline__ uint32_t smem_u32(const void* p) {
    return (uint32_t)__cvta_generic_to_shared(p);
}

#define CP_ASYNC16(dst, src) \
    asm volatile("cp.async.cg.shared.global [%0], [%1], 16;" \
                 :: "r"(dst), "l"(src) : "memory")
#define CP_COMMIT() asm volatile("cp.async.commit_group;" ::: "memory")
#define CP_WAIT0()  asm volatile("cp.async.wait_group 0;" ::: "memory")

__device__ __forceinline__ void ldsm_x4_trans(uint32_t* r, uint32_t a) {
    asm volatile("ldmatrix.sync.aligned.m8n8.x4.trans.shared.b16 {%0,%1,%2,%3}, [%4];"
        : "=r"(r[0]), "=r"(r[1]), "=r"(r[2]), "=r"(r[3]) : "r"(a));
}
__device__ __forceinline__ void ldsm_x4(uint32_t* r, uint32_t a) {
    asm volatile("ldmatrix.sync.aligned.m8n8.x4.shared.b16 {%0,%1,%2,%3}, [%4];"
        : "=r"(r[0]), "=r"(r[1]), "=r"(r[2]), "=r"(r[3]) : "r"(a));
}
__device__ __forceinline__ void mma_bf16(float* d, const uint32_t* a, const uint32_t* b) {
    asm volatile("mma.sync.aligned.m16n8k16.row.col.f32.bf16.bf16.f32 "
        "{%0,%1,%2,%3}, {%4,%5,%6,%7}, {%8,%9}, {%0,%1,%2,%3};"
        : "+f"(d[0]), "+f"(d[1]), "+f"(d[2]), "+f"(d[3])
        : "r"(a[0]), "r"(a[1]), "r"(a[2]), "r"(a[3]), "r"(b[0]), "r"(b[1]));
}

__device__ __forceinline__ float prior_at(const float* __restrict__ prior,
                                          int b, int h, int w) {
    const float s = 31.0f / 127.0f;
    float ys = h * s, xs = w * s;
    int y0 = (int)ys, x0 = (int)xs;
    int y1 = min(y0 + 1, 31), x1 = min(x0 + 1, 31);
    float wy = ys - (float)y0, wx = xs - (float)x0;
    const float* p = prior + b * 1024;
    float p00 = p[y0*32+x0], p01 = p[y0*32+x1];
    float p10 = p[y1*32+x0], p11 = p[y1*32+x1];
    float top = p00 + (p01 - p00) * wx;
    float bot = p10 + (p11 - p10) * wx;
    float v = top + (bot - top) * wy;
    return fminf(1.0f, fmaxf(-1.0f, v));
}

__device__ __forceinline__ void gbarrier(int idx) {
    __syncthreads();
    if (threadIdx.x == 0) {
        __threadfence();
        atomicAdd(&g_bar[idx], 1);
        volatile int* vc = &g_bar[idx];
        while (*vc < NBLK) { }
    }
    __syncthreads();
}

__global__ __launch_bounds__(512, 2) void kfused(
    const float* __restrict__ x, const float* __restrict__ prior,
    const float* __restrict__ Win, const float* __restrict__ b_in,
    const float* __restrict__ A, const float* __restrict__ Bvec,
    const float* __restrict__ alpha_p, const float* __restrict__ gamma_p,
    const float* __restrict__ Wout, const float* __restrict__ b_out,
    float* __restrict__ out)
{
    extern __shared__ __align__(16) char smch[];
    __shared__ float s_pr[128], s_bin[128], s_bo[64];
    __shared__ float s_pow[64], s_cH[128], s_cV[128];

    const int t = threadIdx.x;
    const int wid = t >> 5, lid = t & 31;
    const int bid = blockIdx.x;
    const float alpha = __ldg(alpha_p), gamma = __ldg(gamma_p);

    // ================= PHASE 1: x_proj = F_mod @ Win^T + b_in =================
    {
        __nv_bfloat16* sW  = (__nv_bfloat16*)(smch + P1_SW);
        float*         sXf = (float*)(smch + P1_XF);
        __nv_bfloat16* sF  = (__nv_bfloat16*)(smch + P1_F);
        __nv_bfloat16* sPb = (__nv_bfloat16*)(smch + P1_PB);
        const uint32_t sXf_u = smem_u32(sXf);

#pragma unroll
        for (int i = 0; i < 4; i++) {
            int idx = t + i * 512;           // 2048 = 128o x 16 c4
            int o = idx >> 4, c4 = (idx & 15) * 4;
            float4 wv = *(const float4*)&Win[o * 64 + c4];
            __nv_bfloat162 p0 = __float22bfloat162_rn(make_float2(wv.x, wv.y));
            __nv_bfloat162 p1 = __float22bfloat162_rn(make_float2(wv.z, wv.w));
            *(uint2*)&sW[o * LDB1 + c4] = make_uint2(*(uint32_t*)&p0, *(uint32_t*)&p1);
        }
        if (t < 128) s_bin[t] = b_in[t];

        {   // prologue: prefetch first tile's x row
            int tile = bid;
            const float* xrow = x + (tile >> 7) * 1048576 + (tile & 127) * 128;
#pragma unroll
            for (int i = 0; i < 4; i++) {
                int idx = t + i * 512;
                int c = idx >> 5, ch = (idx & 31) * 4;
                CP_ASYNC16(sXf_u + (uint32_t)(idx * 16), &xrow[c * 16384 + ch]);
            }
            CP_COMMIT();
        }
        __syncthreads();

        for (int tile = bid; tile < NTILE; tile += NBLK) {
            const int b = tile >> 7, h = tile & 127;
            if (t < 128) s_pr[t] = prior_at(prior, b, h, t);
            CP_WAIT0();
            __syncthreads();

#pragma unroll
            for (int i = 0; i < 4; i++) {    // sF <- F_mod bf16 [c][w]
                int idx = t + i * 512;
                int c = idx >> 5, w4 = (idx & 31) * 4;
                float4 f = *(const float4*)&sXf[c * 128 + w4];
                float4 pv = *(const float4*)&s_pr[w4];
                f.x += alpha * pv.x; f.y += alpha * pv.y;
                f.z += alpha * pv.z; f.w += alpha * pv.w;
                __nv_bfloat162 p0 = __float22bfloat162_rn(make_float2(f.x, f.y));
                __nv_bfloat162 p1 = __float22bfloat162_rn(make_float2(f.z, f.w));
                *(uint2*)&sF[c * LDA1 + w4] = make_uint2(*(uint32_t*)&p0, *(uint32_t*)&p1);
            }
            __syncthreads();   // sXf dead from here

            {   // prefetch NEXT tile's x into sXf (overlaps MMA/epilogue/store)
                int nxt = tile + NBLK;
                if (nxt < NTILE) {
                    const float* xrow = x + (nxt >> 7) * 1048576 + (nxt & 127) * 128;
#pragma unroll
                    for (int i = 0; i < 4; i++) {
                        int idx = t + i * 512;
                        int c = idx >> 5, ch = (idx & 31) * 4;
                        CP_ASYNC16(sXf_u + (uint32_t)(idx * 16), &xrow[c * 16384 + ch]);
                    }
                    CP_COMMIT();
                }
            }

            // MMA: m=o (8 m-tiles x 2 w-halves), n=w, K=64
            const int o0 = (wid & 7) * 16;
            const int nh = wid >> 3;
            float acc[8][4];
#pragma unroll
            for (int nt = 0; nt < 8; nt++)
#pragma unroll
                for (int j = 0; j < 4; j++) acc[nt][j] = 0.f;

            const uint32_t sF_u = smem_u32(sF), sW_u = smem_u32(sW);
            const uint32_t a_base = sW_u +
                (uint32_t)(((o0 + (lid & 15)) * LDB1 + ((lid >> 4) << 3)) * 2);
            const int b_row = (lid & 7) + (((lid >> 3) & 1) << 3);
            const int b_col = nh * 64 + ((lid >> 4) << 3);
            const uint32_t b_base = sF_u + (uint32_t)((b_row * LDA1 + b_col) * 2);

#pragma unroll
            for (int ks = 0; ks < 4; ks++) {
                uint32_t afr[4];
                ldsm_x4(afr, a_base + (uint32_t)(ks * 16 * 2));
#pragma unroll
                for (int nt16 = 0; nt16 < 4; nt16++) {
                    uint32_t bfr[4];
                    ldsm_x4_trans(bfr, b_base + (uint32_t)((ks * 16 * LDA1 + nt16 * 16) * 2));
                    mma_bf16(acc[2 * nt16],     afr, bfr);
                    mma_bf16(acc[2 * nt16 + 1], afr, bfr + 2);
                }
            }
            __syncthreads();

            {   // acc (+bias) -> sPb[o][w]
                const int g = lid >> 2, q2 = (lid & 3) * 2;
                const int oA = o0 + g, oB = o0 + g + 8;
                const float bA = s_bin[oA], bB = s_bin[oB];
#pragma unroll
                for (int nt = 0; nt < 8; nt++) {
                    int w = nh * 64 + nt * 8 + q2;
                    __nv_bfloat162 pA = __float22bfloat162_rn(
                        make_float2(acc[nt][0] + bA, acc[nt][1] + bA));
                    __nv_bfloat162 pB = __float22bfloat162_rn(
                        make_float2(acc[nt][2] + bB, acc[nt][3] + bB));
                    *(__nv_bfloat162*)&sPb[oA * LDS1 + w] = pA;
                    *(__nv_bfloat162*)&sPb[oB * LDS1 + w] = pB;
                }
            }
            __syncthreads();

            {   // x_proj write-out
                __nv_bfloat16* xp = g_xp + (b * 128 + h) * 16384;
#pragma unroll
                for (int i = 0; i < 4; i++) {
                    int idx = t + i * 512;
                    int o = idx >> 4, c8 = (idx & 15) * 8;
                    *(uint4*)&xp[o * 128 + c8] = *(const uint4*)&sPb[o * LDS1 + c8];
                }
            }
            __syncthreads();
        }
    }

    gbarrier(0);

    // ===== PHASE 2: dual scan per (b,o) plane (split + pow correction) =====
    {
        __nv_bfloat16* sX = (__nv_bfloat16*)(smch + P2_X);
        __nv_bfloat16* sH = (__nv_bfloat16*)(smch + P2_H);
        __nv_bfloat16* sV = (__nv_bfloat16*)(smch + P2_V);
        const uint32_t sX_u = smem_u32(sX);

        {   // prologue: prefetch first plane
            int pl = bid;
            const __nv_bfloat16* src = g_xp + (pl >> 7) * 2097152 + (pl & 127) * 128;
#pragma unroll
            for (int i = 0; i < 4; i++) {
                int idx = t + i * 512;
                int h = idx >> 4, c8 = (idx & 15) * 8;
                CP_ASYNC16(sX_u + (uint32_t)((h * LDK2 + c8) * 2), &src[h * 16384 + c8]);
            }
            CP_COMMIT();
        }

        for (int pl = bid; pl < NTILE; pl += NBLK) {
            const int b = pl >> 7, o = pl & 127;
            const float a = tanhf(__ldg(&A[o]));
            const float bv = __ldg(&Bvec[o]);
            const int gbase = b * 2097152 + o * 128;

            if (t < 64) {   // s_pow[k] = a^(k+1)
                float p = 1.f, base = a;
                int e = t + 1;
                while (e) { if (e & 1) p *= base; base *= base; e >>= 1; }
                s_pow[t] = p;
            }
            CP_WAIT0();
            __syncthreads();

            if (t < 256) {
                const int row = t & 127, half = t >> 7;
                const __nv_bfloat16* xr = &sX[row * LDK2 + half * 64];
                __nv_bfloat16* hr = &sH[row * LDK2 + half * 64];
                float st = 0.0f;
#pragma unroll 4
                for (int wb = 0; wb < 16; wb++) {
                    uint2 u = *(const uint2*)&xr[wb * 4];
                    float2 f0 = __bfloat1622float2(*(__nv_bfloat162*)&u.x);
                    float2 f1 = __bfloat1622float2(*(__nv_bfloat162*)&u.y);
                    st = fmaf(a, st, bv * f0.x); f0.x = st;
                    st = fmaf(a, st, bv * f0.y); f0.y = st;
                    st = fmaf(a, st, bv * f1.x); f1.x = st;
                    st = fmaf(a, st, bv * f1.y); f1.y = st;
                    __nv_bfloat162 p0 = __float22bfloat162_rn(f0);
                    __nv_bfloat162 p1 = __float22bfloat162_rn(f1);
                    *(uint2*)&hr[wb * 4] = make_uint2(*(uint32_t*)&p0, *(uint32_t*)&p1);
                }
                if (half == 0) s_cH[row] = st;
            } else {
                const int idx = t - 256;
                const int col = idx & 127, half = idx >> 7;
                const int h0 = half * 64;
                float st = 0.0f;
#pragma unroll 4
                for (int j = 0; j < 64; j++) {
                    int h = h0 + j;
                    float xvv = __bfloat162float(sX[h * LDK2 + col]);
                    st = fmaf(a, st, bv * xvv);
                    sV[h * LDK2 + col] = __float2bfloat16(st);
                }
                if (half == 0) s_cV[col] = st;
            }
            __syncthreads();   // sX dead from here (merge reads sH/sV only)

            {   // prefetch NEXT plane into sX (overlaps merge+store)
                int nxt = pl + NBLK;
                if (nxt < NTILE) {
                    const __nv_bfloat16* src =
                        g_xp + (nxt >> 7) * 2097152 + (nxt & 127) * 128;
#pragma unroll
                    for (int i = 0; i < 4; i++) {
                        int idx = t + i * 512;
                        int h = idx >> 4, c8 = (idx & 15) * 8;
                        CP_ASYNC16(sX_u + (uint32_t)((h * LDK2 + c8) * 2),
                                   &src[h * 16384 + c8]);
                    }
                    CP_COMMIT();
                }
            }

            {   // merge + corrections + store
                __nv_bfloat16* dst = g_hs + gbase;
#pragma unroll
                for (int i = 0; i < 4; i++) {
                    int idx = t + i * 512;
                    int h = idx >> 4, c8 = (idx & 15) * 8;
                    uint4 uh = *(const uint4*)&sH[h * LDK2 + c8];
                    uint4 uv = *(const uint4*)&sV[h * LDK2 + c8];
                    float2 h0 = __bfloat1622float2(*(__nv_bfloat162*)&uh.x);
                    float2 h1 = __bfloat1622float2(*(__nv_bfloat162*)&uh.y);
                    float2 h2 = __bfloat1622float2(*(__nv_bfloat162*)&uh.z);
                    float2 h3 = __bfloat1622float2(*(__nv_bfloat162*)&uh.w);
                    float2 v0 = __bfloat1622float2(*(__nv_bfloat162*)&uv.x);
                    float2 v1 = __bfloat1622float2(*(__nv_bfloat162*)&uv.y);
                    float2 v2 = __bfloat1622float2(*(__nv_bfloat162*)&uv.z);
                    float2 v3 = __bfloat1622float2(*(__nv_bfloat162*)&uv.w);
                    float fv[8] = { h0.x+v0.x, h0.y+v0.y, h1.x+v1.x, h1.y+v1.y,
                                    h2.x+v2.x, h2.y+v2.y, h3.x+v3.x, h3.y+v3.y };
                    if (c8 >= 64) {
                        float ch = s_cH[h];
                        float4 pw0 = *(const float4*)&s_pow[c8 - 64];
                        float4 pw1 = *(const float4*)&s_pow[c8 - 60];
                        fv[0] = fmaf(pw0.x, ch, fv[0]);
                        fv[1] = fmaf(pw0.y, ch, fv[1]);
                        fv[2] = fmaf(pw0.z, ch, fv[2]);
                        fv[3] = fmaf(pw0.w, ch, fv[3]);
                        fv[4] = fmaf(pw1.x, ch, fv[4]);
                        fv[5] = fmaf(pw1.y, ch, fv[5]);
                        fv[6] = fmaf(pw1.z, ch, fv[6]);
                        fv[7] = fmaf(pw1.w, ch, fv[7]);
                    }
                    if (h >= 64) {
                        float ph = s_pow[h - 64];
                        float4 cv0 = *(const float4*)&s_cV[c8];
                        float4 cv1 = *(const float4*)&s_cV[c8 + 4];
                        fv[0] = fmaf(ph, cv0.x, fv[0]);
                        fv[1] = fmaf(ph, cv0.y, fv[1]);
                        fv[2] = fmaf(ph, cv0.z, fv[2]);
                        fv[3] = fmaf(ph, cv0.w, fv[3]);
                        fv[4] = fmaf(ph, cv1.x, fv[4]);
                        fv[5] = fmaf(ph, cv1.y, fv[5]);
                        fv[6] = fmaf(ph, cv1.z, fv[6]);
                        fv[7] = fmaf(ph, cv1.w, fv[7]);
                    }
                    uint4 r;
                    __nv_bfloat162 q0 = __float22bfloat162_rn(make_float2(fv[0], fv[1]));
                    __nv_bfloat162 q1 = __float22bfloat162_rn(make_float2(fv[2], fv[3]));
                    __nv_bfloat162 q2 = __float22bfloat162_rn(make_float2(fv[4], fv[5]));
                    __nv_bfloat162 q3 = __float22bfloat162_rn(make_float2(fv[6], fv[7]));
                    r.x = *(uint32_t*)&q0; r.y = *(uint32_t*)&q1;
                    r.z = *(uint32_t*)&q2; r.w = *(uint32_t*)&q3;
                    *(uint4*)&dst[h * 16384 + c8] = r;
                }
            }
            __syncthreads();
        }
    }

    gbarrier(1);

    // ================= PHASE 3: out = x + a*pr + g*(h_sum @ Wout^T + b) ======
    {
        __nv_bfloat16* sWo = (__nv_bfloat16*)(smch + P3_WO);
        __nv_bfloat16* sHs = (__nv_bfloat16*)(smch + P3_HS);
        float* sR = (float*)(smch + P3_R);
        const uint32_t sHs_u = smem_u32(sHs);

#pragma unroll
        for (int i = 0; i < 4; i++) {
            int idx = t + i * 512;           // 2048 = 64c x 32 o4
            int c = idx >> 5, o4 = (idx & 31) * 4;
            float4 wv = *(const float4*)&Wout[c * 128 + o4];
            __nv_bfloat162 p0 = __float22bfloat162_rn(make_float2(wv.x, wv.y));
            __nv_bfloat162 p1 = __float22bfloat162_rn(make_float2(wv.z, wv.w));
            *(uint2*)&sWo[c * LDB3 + o4] = make_uint2(*(uint32_t*)&p0, *(uint32_t*)&p1);
        }
        if (t < 64) s_bo[t] = b_out[t];

        {   // prologue: prefetch first tile's h_sum
            int tile = bid;
            const __nv_bfloat16* hs = g_hs + ((tile >> 7) * 128 + (tile & 127)) * 16384;
#pragma unroll
            for (int i = 0; i < 4; i++) {
                int idx = t + i * 512;
                int o = idx >> 4, w8 = (idx & 15) * 8;
                CP_ASYNC16(sHs_u + (uint32_t)((o * LDA3 + w8) * 2), &hs[o * 128 + w8]);
            }
            CP_COMMIT();
        }
        __syncthreads();

        for (int tile = bid; tile < NTILE; tile += NBLK) {
            const int b = tile >> 7, h = tile & 127;
            const int base_bh = b * 1048576 + h * 128;

            if (t < 128) s_pr[t] = prior_at(prior, b, h, t);

            float4 xv[4];
#pragma unroll
            for (int i = 0; i < 4; i++) {
                int idx = t + i * 512;
                int c = idx >> 5, w4 = (idx & 31) * 4;
                xv[i] = *(const float4*)&x[base_bh + c * 16384 + w4];
            }
            CP_WAIT0();
            __syncthreads();

            // MMA: m=c (4 m-tiles x 4 w-quarters), n=w, K=128
            const int c0 = (wid & 3) * 16;
            const int q = wid >> 2;
            float acc[4][4];
#pragma unroll
            for (int nt = 0; nt < 4; nt++)
#pragma unroll
                for (int j = 0; j < 4; j++) acc[nt][j] = 0.f;

            const uint32_t sWo_u = smem_u32(sWo);
            const uint32_t a_base = sWo_u +
                (uint32_t)(((c0 + (lid & 15)) * LDB3 + ((lid >> 4) << 3)) * 2);
            const int b_row = (lid & 7) + (((lid >> 3) & 1) << 3);
            const int b_col = q * 32 + ((lid >> 4) << 3);
            const uint32_t b_base = sHs_u + (uint32_t)((b_row * LDA3 + b_col) * 2);

#pragma unroll
            for (int ks = 0; ks < 8; ks++) {
                uint32_t afr[4];
                ldsm_x4(afr, a_base + (uint32_t)(ks * 16 * 2));
#pragma unroll
                for (int nt16 = 0; nt16 < 2; nt16++) {
                    uint32_t bfr[4];
                    ldsm_x4_trans(bfr, b_base + (uint32_t)((ks * 16 * LDA3 + nt16 * 16) * 2));
                    mma_bf16(acc[2 * nt16],     afr, bfr);
                    mma_bf16(acc[2 * nt16 + 1], afr, bfr + 2);
                }
            }
            __syncthreads();   // sHs dead from here (sR is separate region)

            {   // prefetch NEXT tile's h_sum into sHs (overlaps epilogue)
                int nxt = tile + NBLK;
                if (nxt < NTILE) {
                    const __nv_bfloat16* hs =
                        g_hs + ((nxt >> 7) * 128 + (nxt & 127)) * 16384;
#pragma unroll
                    for (int i = 0; i < 4; i++) {
                        int idx = t + i * 512;
                        int o = idx >> 4, w8 = (idx & 15) * 8;
                        CP_ASYNC16(sHs_u + (uint32_t)((o * LDA3 + w8) * 2),
                                   &hs[o * 128 + w8]);
                    }
                    CP_COMMIT();
                }
            }

            {   // acc -> sR[c][w]
                const int g = lid >> 2, q2 = (lid & 3) * 2;
                const int cA = c0 + g, cB = c0 + g + 8;
#pragma unroll
                for (int nt = 0; nt < 4; nt++) {
                    int w = q * 32 + nt * 8 + q2;
                    *(float2*)&sR[cA * LDP + w] = make_float2(acc[nt][0], acc[nt][1]);
                    *(float2*)&sR[cB * LDP + w] = make_float2(acc[nt][2], acc[nt][3]);
                }
            }
            __syncthreads();

            {   // fused epilogue
#pragma unroll
                for (int i = 0; i < 4; i++) {
                    int idx = t + i * 512;
                    int c = idx >> 5, w4 = (idx & 31) * 4;
                    int gb = base_bh + c * 16384 + w4;
                    float4 rv = *(const float4*)&sR[c * LDP + w4];
                    float4 pv = *(const float4*)&s_pr[w4];
                    float bo = s_bo[c];
                    float4 r;
                    r.x = fmaf(alpha, pv.x, xv[i].x) + gamma * (rv.x + bo);
                    r.y = fmaf(alpha, pv.y, xv[i].y) + gamma * (rv.y + bo);
                    r.z = fmaf(alpha, pv.z, xv[i].z) + gamma * (rv.z + bo);
                    r.w = fmaf(alpha, pv.w, xv[i].w) + gamma * (rv.w + bo);
                    *(float4*)&out[gb] = r;
                }
            }
            __syncthreads();
        }
    }
}

extern "C" void kernel_launch(void* const* d_in, const int* in_sizes, int n_in,
                              void* d_out, int out_size) {
    const float* x      = (const float*)d_in[0];
    const float* prior  = (const float*)d_in[1];
    const float* W_in   = (const float*)d_in[2];
    const float* b_in   = (const float*)d_in[3];
    const float* A      = (const float*)d_in[4];
    const float* B      = (const float*)d_in[5];
    const float* alpha  = (const float*)d_in[6];
    const float* gamma  = (const float*)d_in[7];
    const float* W_out  = (const float*)d_in[8];
    const float* b_out  = (const float*)d_in[9];
    float* out = (float*)d_out;

    void* bar_addr = nullptr;
    cudaGetSymbolAddress(&bar_addr, g_bar);
    cudaMemsetAsync(bar_addr, 0, 2 * sizeof(int));

    const int smem = 104448;
    cudaFuncSetAttribute(kfused, cudaFuncAttributeMaxDynamicSharedMemorySize, smem);
    kfused<<<NBLK, 512, smem>>>(x, prior, W_in, b_in, A, B,
                                alpha, gamma, W_out, b_out, out);
}